// round 16
// baseline (speedup 1.0000x reference)
#include <cuda_runtime.h>
#include <cstdint>

// TorchWrithe: writhe of all non-adjacent segment pairs per frame.
// B=128, N=300, SEG_LEN=1 -> S=44253 pairs, out (B,S) f32.
//
// R15 best config (packed f32x2, PAIRS=2, interleaved LDS.64 slab, 3-cross
// direct-dot basis, inline branchless (i,j) inversion) with two ILP changes:
//  - ALL 24 coordinate LDS.64 (both pg iterations) issued up front under an
//    85-reg budget (launch_bounds 128,6), collapsing two LDS-latency
//    exposures into one and letting ptxas interleave the two iterations.
//  - Estrin-split asin polynomial (same op count, half the chain depth).

#define N_FRAMES_C 128
#define N_ATOMS_C  300
#define S_PAIRS_C  44253
#define BLOCK_T 128
#define F_TILE 4
#define PAIRS (F_TILE / 2)                        // 2
#define FLOATS_PER_FRAME (N_ATOMS_C * 3)          // 900
#define VEC4_PER_FRAME (FLOATS_PER_FRAME / 4)     // 225
#define SLAB_STRIDE_B (FLOATS_PER_FRAME * 8)      // 7200 bytes per pg slab

__device__ __forceinline__ int fcum(int i) {
    return 297 * i - (i * (i - 1)) / 2;
}

// ---------- packed f32x2 primitives ----------
struct P2 { unsigned long long v; };

__device__ __forceinline__ P2 pk(float lo, float hi) {
    P2 r; asm("mov.b64 %0,{%1,%2};" : "=l"(r.v) : "f"(lo), "f"(hi)); return r;
}
__device__ __forceinline__ void up(P2 p, float& lo, float& hi) {
    asm("mov.b64 {%0,%1},%2;" : "=f"(lo), "=f"(hi) : "l"(p.v));
}
__device__ __forceinline__ P2 fma2(P2 a, P2 b, P2 c) {
    P2 r; asm("fma.rn.f32x2 %0,%1,%2,%3;" : "=l"(r.v) : "l"(a.v), "l"(b.v), "l"(c.v));
    return r;
}
__device__ __forceinline__ P2 mul2(P2 a, P2 b) {
    P2 r; asm("mul.rn.f32x2 %0,%1,%2;" : "=l"(r.v) : "l"(a.v), "l"(b.v));
    return r;
}
__device__ __forceinline__ P2 add2(P2 a, P2 b) {
    P2 r; asm("add.rn.f32x2 %0,%1,%2;" : "=l"(r.v) : "l"(a.v), "l"(b.v));
    return r;
}
__device__ __forceinline__ P2 c2(float x) { return pk(x, x); }

template <int OFF>
__device__ __forceinline__ P2 lds64(uint32_t base) {
    P2 r; asm("ld.shared.b64 %0,[%1+%2];" : "=l"(r.v) : "r"(base), "n"(OFF));
    return r;
}

struct V3P { P2 x, y, z; };

__device__ __forceinline__ P2 sub2_(P2 a, P2 b, P2 NEG1) { return fma2(b, NEG1, a); }

__device__ __forceinline__ V3P vsub2(V3P a, V3P b, P2 NEG1) {
    return { sub2_(a.x, b.x, NEG1), sub2_(a.y, b.y, NEG1), sub2_(a.z, b.z, NEG1) };
}
__device__ __forceinline__ V3P vcross2(V3P a, V3P b, P2 NEG1) {
    V3P r;
    r.x = sub2_(mul2(a.y, b.z), mul2(a.z, b.y), NEG1);
    r.y = sub2_(mul2(a.z, b.x), mul2(a.x, b.z), NEG1);
    r.z = sub2_(mul2(a.x, b.y), mul2(a.y, b.x), NEG1);
    return r;
}
__device__ __forceinline__ P2 vdot2(V3P a, V3P b) {
    return fma2(a.z, b.z, fma2(a.y, b.y, mul2(a.x, b.x)));
}

__device__ __forceinline__ float sqrt_approx(float x) {
    float r; asm("sqrt.approx.f32 %0,%1;" : "=f"(r) : "f"(x)); return r;
}

// Packed asin via A&S 4.4.46 (deg-7), Estrin-split for chain depth:
// asin(a) = pi/2 - sqrt(1-a)*P(a), a in [0,1], |err|<=2e-8. We evaluate
// Pneg = -P as (q0 + b*(q1 + b*(q2 + b*q3))) with b=a^2, q_k = c_{2k} +
// c_{2k+1}*a (4 independent pair-FMAs, then a 3-deep chain). Magnitude
// result >= 0, so sign restore is an OR of t's sign bits.
__device__ __forceinline__ P2 asin2(P2 t, P2 ONE, P2 NEG1, P2 HALFPI) {
    P2 a; a.v = t.v & 0x7FFFFFFF7FFFFFFFull;      // |t| both lanes
    P2 m = fma2(a, NEG1, ONE);                    // 1 - |t|
    float ml, mh; up(m, ml, mh);
    float sl = sqrt_approx(fmaxf(ml, 0.0f));      // sqrt(1-|t|)
    float sh = sqrt_approx(fmaxf(mh, 0.0f));
    P2 s = pk(sl, sh);
    P2 b  = mul2(a, a);
    P2 q0 = fma2(c2( 0.2145988016f), a, c2(-1.5707963050f));
    P2 q1 = fma2(c2( 0.0501743046f), a, c2(-0.0889789874f));
    P2 q2 = fma2(c2( 0.0170881256f), a, c2(-0.0308918810f));
    P2 q3 = fma2(c2( 0.0012624911f), a, c2(-0.0066700901f));
    P2 p  = fma2(q3, b, q2);
    p     = fma2(p,  b, q1);
    p     = fma2(p,  b, q0);                      // Pneg(a)
    P2 r = fma2(s, p, HALFPI);                    // >= 0
    r.v |= (t.v & 0x8000000080000000ull);         // copysign (r >= 0)
    return r;
}

__global__ __launch_bounds__(BLOCK_T, 6)
void writhe_kernel(const float* __restrict__ xyz, float* __restrict__ out) {
    // Interleaved slab: sm2[pg*900 + k] = {frame(2pg)[k], frame(2pg+1)[k]}.
    __shared__ float2 sm2[PAIRS * FLOATS_PER_FRAME];   // 14400 B

    const int b0 = blockIdx.y * F_TILE;
    #pragma unroll
    for (int pg = 0; pg < PAIRS; ++pg) {
        const float4* __restrict__ fA =
            (const float4*)(xyz + (size_t)(b0 + 2 * pg) * FLOATS_PER_FRAME);
        const float4* __restrict__ fB =
            (const float4*)(xyz + (size_t)(b0 + 2 * pg + 1) * FLOATS_PER_FRAME);
        #pragma unroll
        for (int k = 0; k < 2; ++k) {
            int kq = threadIdx.x + k * BLOCK_T;
            if (kq < VEC4_PER_FRAME) {
                float4 a = fA[kq];
                float4 c = fB[kq];
                float2* d = &sm2[pg * FLOATS_PER_FRAME + 4 * kq];
                d[0] = make_float2(a.x, c.x);
                d[1] = make_float2(a.y, c.y);
                d[2] = make_float2(a.z, c.z);
                d[3] = make_float2(a.w, c.w);
            }
        }
    }
    __syncthreads();

    const int s = blockIdx.x * BLOCK_T + threadIdx.x;
    if (s >= S_PAIRS_C) return;

    // Closed-form s -> (i, j), branchless single-step fixup.
    float rr = sqrt_approx(354025.0f - 8.0f * (float)s);
    int i = (int)((595.0f - rr) * 0.5f);
    i = min(max(i, 0), 296);
    i += (fcum(i + 1) <= s);
    i -= (fcum(i) > s);
    const int j = (s - fcum(i)) + i + 2;

    const uint32_t smbase = (uint32_t)__cvta_generic_to_shared(sm2);
    const uint32_t oi = smbase + 24u * (uint32_t)i;     // 3*i float2 (8B each)
    const uint32_t oj = smbase + 24u * (uint32_t)j;

    float* __restrict__ op = out + (size_t)b0 * S_PAIRS_C + s;

    const P2 ONE    = c2(1.0f);
    const P2 NEG1   = c2(-1.0f);
    const P2 HALFPI = c2(1.5707963267948966f);
    const float K = 0.15915494309189535f;

    // ---- batch-prefetch: all 24 coordinate LDS.64 for BOTH iterations ----
    V3P p0[PAIRS], p1[PAIRS], p2[PAIRS], p3[PAIRS];
    p0[0] = { lds64<0>(oi),                 lds64<8>(oi),                 lds64<16>(oi) };
    p1[0] = { lds64<24>(oi),                lds64<32>(oi),                lds64<40>(oi) };
    p2[0] = { lds64<0>(oj),                 lds64<8>(oj),                 lds64<16>(oj) };
    p3[0] = { lds64<24>(oj),                lds64<32>(oj),                lds64<40>(oj) };
    p0[1] = { lds64<SLAB_STRIDE_B+0>(oi),   lds64<SLAB_STRIDE_B+8>(oi),   lds64<SLAB_STRIDE_B+16>(oi) };
    p1[1] = { lds64<SLAB_STRIDE_B+24>(oi),  lds64<SLAB_STRIDE_B+32>(oi),  lds64<SLAB_STRIDE_B+40>(oi) };
    p2[1] = { lds64<SLAB_STRIDE_B+0>(oj),   lds64<SLAB_STRIDE_B+8>(oj),   lds64<SLAB_STRIDE_B+16>(oj) };
    p3[1] = { lds64<SLAB_STRIDE_B+24>(oj),  lds64<SLAB_STRIDE_B+32>(oj),  lds64<SLAB_STRIDE_B+40>(oj) };

    #pragma unroll
    for (int pg = 0; pg < PAIRS; ++pg) {
        V3P w  = vsub2(p1[pg], p0[pg], NEG1);
        V3P u  = vsub2(p3[pg], p2[pg], NEG1);
        V3P v0 = vsub2(p2[pg], p0[pg], NEG1);

        V3P A = vcross2(v0, w, NEG1);
        V3P B = vcross2(v0, u, NEG1);
        V3P C = vcross2(w,  u, NEG1);

        V3P c1 = vsub2(B, C, NEG1);            // c1 = B - C
        V3P cm = vsub2(A, C, NEG1);            // c2 = A - C

        // Direct dot products (no cancellation-prone combos).
        P2 aa  = vdot2(A, A);                  // n0
        P2 bb  = vdot2(B, B);                  // n3
        P2 n1  = vdot2(c1, c1);
        P2 n2  = vdot2(cm, cm);
        P2 e01 = vdot2(A, c1);                 // d01 = -e01
        P2 d12 = vdot2(c1, cm);
        P2 e23 = vdot2(cm, B);                 // d23 = -e23
        P2 ab  = vdot2(A, B);                  // d30
        P2 au  = vdot2(A, u);                  // sign = sign(-au)

        P2 q01 = mul2(aa, n1);
        P2 q12 = mul2(n1, n2);
        P2 q23 = mul2(n2, bb);
        P2 q30 = mul2(bb, aa);
        float ql, qh;
        up(q01, ql, qh); P2 r01 = pk(-rsqrtf(ql), -rsqrtf(qh));  // neg folds d01
        up(q12, ql, qh); P2 r12 = pk( rsqrtf(ql),  rsqrtf(qh));
        up(q23, ql, qh); P2 r23 = pk(-rsqrtf(ql), -rsqrtf(qh));  // neg folds d23
        up(q30, ql, qh); P2 r30 = pk( rsqrtf(ql),  rsqrtf(qh));

        P2 t0 = mul2(e01, r01);
        P2 t1 = mul2(d12, r12);
        P2 t2 = mul2(e23, r23);
        P2 t3 = mul2(ab,  r30);

        P2 omega = add2(add2(asin2(t0, ONE, NEG1, HALFPI),
                             asin2(t1, ONE, NEG1, HALFPI)),
                        add2(asin2(t2, ONE, NEG1, HALFPI),
                             asin2(t3, ONE, NEG1, HALFPI)));

        // sign(dot(c0, v2)) = sign(-au); fold 1/(2pi).
        float aul, auh; up(au, aul, auh);
        float gl = (aul < 0.0f) ? K : ((aul > 0.0f) ? -K : 0.0f);
        float gh = (auh < 0.0f) ? K : ((auh > 0.0f) ? -K : 0.0f);
        P2 res = mul2(omega, pk(gl, gh));

        float rl, rh; up(res, rl, rh);
        op[(size_t)(2 * pg)     * S_PAIRS_C] = rl;
        op[(size_t)(2 * pg + 1) * S_PAIRS_C] = rh;
    }
}

extern "C" void kernel_launch(void* const* d_in, const int* in_sizes, int n_in,
                              void* d_out, int out_size) {
    const float* xyz = (const float*)d_in[0];
    float* out = (float*)d_out;
    dim3 grid((S_PAIRS_C + BLOCK_T - 1) / BLOCK_T, N_FRAMES_C / F_TILE);
    writhe_kernel<<<grid, BLOCK_T>>>(xyz, out);
}

// round 17
// speedup vs baseline: 1.0393x; 1.0393x over previous
#include <cuda_runtime.h>
#include <cstdint>

// TorchWrithe: writhe of all non-adjacent segment pairs per frame.
// B=128, N=300, SEG_LEN=1 -> S=44253 pairs, out (B,S) f32.
//
// R15 best config (packed f32x2, PAIRS=2, interleaved LDS.64 slab, 3-cross
// direct-dot basis, inline branchless (i,j) inversion) with:
//  - BLOCK_T=256: halves the x-block count -> per-block smem fill and
//    prologue amortize over 2x the pairs (fill slots/pf and L2 fill traffic
//    both halve). Occupancy unchanged (32 warps/SM either way).
//  - Estrin-split asin polynomial (same ops, half the chain depth).

#define N_FRAMES_C 128
#define N_ATOMS_C  300
#define S_PAIRS_C  44253
#define BLOCK_T 256
#define F_TILE 4
#define PAIRS (F_TILE / 2)                        // 2
#define FLOATS_PER_FRAME (N_ATOMS_C * 3)          // 900
#define VEC4_PER_FRAME (FLOATS_PER_FRAME / 4)     // 225

__device__ __forceinline__ int fcum(int i) {
    return 297 * i - (i * (i - 1)) / 2;
}

// ---------- packed f32x2 primitives ----------
struct P2 { unsigned long long v; };

__device__ __forceinline__ P2 pk(float lo, float hi) {
    P2 r; asm("mov.b64 %0,{%1,%2};" : "=l"(r.v) : "f"(lo), "f"(hi)); return r;
}
__device__ __forceinline__ void up(P2 p, float& lo, float& hi) {
    asm("mov.b64 {%0,%1},%2;" : "=f"(lo), "=f"(hi) : "l"(p.v));
}
__device__ __forceinline__ P2 fma2(P2 a, P2 b, P2 c) {
    P2 r; asm("fma.rn.f32x2 %0,%1,%2,%3;" : "=l"(r.v) : "l"(a.v), "l"(b.v), "l"(c.v));
    return r;
}
__device__ __forceinline__ P2 mul2(P2 a, P2 b) {
    P2 r; asm("mul.rn.f32x2 %0,%1,%2;" : "=l"(r.v) : "l"(a.v), "l"(b.v));
    return r;
}
__device__ __forceinline__ P2 add2(P2 a, P2 b) {
    P2 r; asm("add.rn.f32x2 %0,%1,%2;" : "=l"(r.v) : "l"(a.v), "l"(b.v));
    return r;
}
__device__ __forceinline__ P2 c2(float x) { return pk(x, x); }

template <int OFF>
__device__ __forceinline__ P2 lds64(uint32_t base) {
    P2 r; asm("ld.shared.b64 %0,[%1+%2];" : "=l"(r.v) : "r"(base), "n"(OFF));
    return r;
}

struct V3P { P2 x, y, z; };

__device__ __forceinline__ P2 sub2_(P2 a, P2 b, P2 NEG1) { return fma2(b, NEG1, a); }

__device__ __forceinline__ V3P vsub2(V3P a, V3P b, P2 NEG1) {
    return { sub2_(a.x, b.x, NEG1), sub2_(a.y, b.y, NEG1), sub2_(a.z, b.z, NEG1) };
}
__device__ __forceinline__ V3P vcross2(V3P a, V3P b, P2 NEG1) {
    V3P r;
    r.x = sub2_(mul2(a.y, b.z), mul2(a.z, b.y), NEG1);
    r.y = sub2_(mul2(a.z, b.x), mul2(a.x, b.z), NEG1);
    r.z = sub2_(mul2(a.x, b.y), mul2(a.y, b.x), NEG1);
    return r;
}
__device__ __forceinline__ P2 vdot2(V3P a, V3P b) {
    return fma2(a.z, b.z, fma2(a.y, b.y, mul2(a.x, b.x)));
}

__device__ __forceinline__ float sqrt_approx(float x) {
    float r; asm("sqrt.approx.f32 %0,%1;" : "=f"(r) : "f"(x)); return r;
}

// Packed asin via A&S 4.4.46 (deg-7), Estrin-split:
// asin(a) = pi/2 - sqrt(1-a)*P(a), a in [0,1], |err|<=2e-8. Pneg = -P is
// evaluated as q0 + b*(q1 + b*(q2 + b*q3)), b=a^2, q_k independent pair-FMAs.
// Magnitude result >= 0, so sign restore is an OR of t's sign bits.
// |t| slightly > 1 from rounding clamps to +-pi/2 via fmaxf(1-a, 0).
__device__ __forceinline__ P2 asin2(P2 t, P2 ONE, P2 NEG1, P2 HALFPI) {
    P2 a; a.v = t.v & 0x7FFFFFFF7FFFFFFFull;      // |t| both lanes
    P2 m = fma2(a, NEG1, ONE);                    // 1 - |t|
    float ml, mh; up(m, ml, mh);
    float sl = sqrt_approx(fmaxf(ml, 0.0f));      // sqrt(1-|t|)
    float sh = sqrt_approx(fmaxf(mh, 0.0f));
    P2 s = pk(sl, sh);
    P2 b  = mul2(a, a);
    P2 q0 = fma2(c2( 0.2145988016f), a, c2(-1.5707963050f));
    P2 q1 = fma2(c2( 0.0501743046f), a, c2(-0.0889789874f));
    P2 q2 = fma2(c2( 0.0170881256f), a, c2(-0.0308918810f));
    P2 q3 = fma2(c2( 0.0012624911f), a, c2(-0.0066700901f));
    P2 p  = fma2(q3, b, q2);
    p     = fma2(p,  b, q1);
    p     = fma2(p,  b, q0);                      // Pneg(a)
    P2 r = fma2(s, p, HALFPI);                    // >= 0
    r.v |= (t.v & 0x8000000080000000ull);         // copysign (r >= 0)
    return r;
}

__global__ __launch_bounds__(BLOCK_T, 4)
void writhe_kernel(const float* __restrict__ xyz, float* __restrict__ out) {
    // Interleaved slab: sm2[pg*900 + k] = {frame(2pg)[k], frame(2pg+1)[k]}.
    __shared__ float2 sm2[PAIRS * FLOATS_PER_FRAME];   // 14400 B

    const int b0 = blockIdx.y * F_TILE;
    #pragma unroll
    for (int pg = 0; pg < PAIRS; ++pg) {
        const float4* __restrict__ fA =
            (const float4*)(xyz + (size_t)(b0 + 2 * pg) * FLOATS_PER_FRAME);
        const float4* __restrict__ fB =
            (const float4*)(xyz + (size_t)(b0 + 2 * pg + 1) * FLOATS_PER_FRAME);
        int kq = threadIdx.x;
        if (kq < VEC4_PER_FRAME) {
            float4 a = fA[kq];
            float4 c = fB[kq];
            float2* d = &sm2[pg * FLOATS_PER_FRAME + 4 * kq];
            d[0] = make_float2(a.x, c.x);
            d[1] = make_float2(a.y, c.y);
            d[2] = make_float2(a.z, c.z);
            d[3] = make_float2(a.w, c.w);
        }
    }
    __syncthreads();

    const int s = blockIdx.x * BLOCK_T + threadIdx.x;
    if (s >= S_PAIRS_C) return;

    // Closed-form s -> (i, j), branchless single-step fixup.
    float rr = sqrt_approx(354025.0f - 8.0f * (float)s);
    int i = (int)((595.0f - rr) * 0.5f);
    i = min(max(i, 0), 296);
    i += (fcum(i + 1) <= s);
    i -= (fcum(i) > s);
    const int j = (s - fcum(i)) + i + 2;

    const uint32_t smbase = (uint32_t)__cvta_generic_to_shared(sm2);
    const uint32_t oi0 = smbase + 24u * (uint32_t)i;    // 3*i float2 (8B each)
    const uint32_t oj0 = smbase + 24u * (uint32_t)j;

    float* __restrict__ op = out + (size_t)b0 * S_PAIRS_C + s;

    const P2 ONE    = c2(1.0f);
    const P2 NEG1   = c2(-1.0f);
    const P2 HALFPI = c2(1.5707963267948966f);
    const float K = 0.15915494309189535f;

    #pragma unroll
    for (int pg = 0; pg < PAIRS; ++pg) {
        const uint32_t oi = oi0 + pg * FLOATS_PER_FRAME * 8;
        const uint32_t oj = oj0 + pg * FLOATS_PER_FRAME * 8;

        // Packed coords: lane-lo = frame 2pg, lane-hi = frame 2pg+1.
        V3P p0 = { lds64< 0>(oi), lds64< 8>(oi), lds64<16>(oi) };
        V3P p1 = { lds64<24>(oi), lds64<32>(oi), lds64<40>(oi) };
        V3P p2 = { lds64< 0>(oj), lds64< 8>(oj), lds64<16>(oj) };
        V3P p3 = { lds64<24>(oj), lds64<32>(oj), lds64<40>(oj) };

        V3P w  = vsub2(p1, p0, NEG1);
        V3P u  = vsub2(p3, p2, NEG1);
        V3P v0 = vsub2(p2, p0, NEG1);

        V3P A = vcross2(v0, w, NEG1);
        V3P B = vcross2(v0, u, NEG1);
        V3P C = vcross2(w,  u, NEG1);

        V3P c1 = vsub2(B, C, NEG1);            // c1 = B - C
        V3P cm = vsub2(A, C, NEG1);            // c2 = A - C

        // Direct dot products (no cancellation-prone combos).
        P2 aa  = vdot2(A, A);                  // n0
        P2 bb  = vdot2(B, B);                  // n3
        P2 n1  = vdot2(c1, c1);
        P2 n2  = vdot2(cm, cm);
        P2 e01 = vdot2(A, c1);                 // d01 = -e01
        P2 d12 = vdot2(c1, cm);
        P2 e23 = vdot2(cm, B);                 // d23 = -e23
        P2 ab  = vdot2(A, B);                  // d30
        P2 au  = vdot2(A, u);                  // sign = sign(-au)

        P2 q01 = mul2(aa, n1);
        P2 q12 = mul2(n1, n2);
        P2 q23 = mul2(n2, bb);
        P2 q30 = mul2(bb, aa);
        float ql, qh;
        up(q01, ql, qh); P2 r01 = pk(-rsqrtf(ql), -rsqrtf(qh));  // neg folds d01
        up(q12, ql, qh); P2 r12 = pk( rsqrtf(ql),  rsqrtf(qh));
        up(q23, ql, qh); P2 r23 = pk(-rsqrtf(ql), -rsqrtf(qh));  // neg folds d23
        up(q30, ql, qh); P2 r30 = pk( rsqrtf(ql),  rsqrtf(qh));

        P2 t0 = mul2(e01, r01);
        P2 t1 = mul2(d12, r12);
        P2 t2 = mul2(e23, r23);
        P2 t3 = mul2(ab,  r30);

        P2 omega = add2(add2(asin2(t0, ONE, NEG1, HALFPI),
                             asin2(t1, ONE, NEG1, HALFPI)),
                        add2(asin2(t2, ONE, NEG1, HALFPI),
                             asin2(t3, ONE, NEG1, HALFPI)));

        // sign(dot(c0, v2)) = sign(-au); fold 1/(2pi).
        float aul, auh; up(au, aul, auh);
        float gl = (aul < 0.0f) ? K : ((aul > 0.0f) ? -K : 0.0f);
        float gh = (auh < 0.0f) ? K : ((auh > 0.0f) ? -K : 0.0f);
        P2 res = mul2(omega, pk(gl, gh));

        float rl, rh; up(res, rl, rh);
        op[(size_t)(2 * pg)     * S_PAIRS_C] = rl;
        op[(size_t)(2 * pg + 1) * S_PAIRS_C] = rh;
    }
}

extern "C" void kernel_launch(void* const* d_in, const int* in_sizes, int n_in,
                              void* d_out, int out_size) {
    const float* xyz = (const float*)d_in[0];
    float* out = (float*)d_out;
    dim3 grid((S_PAIRS_C + BLOCK_T - 1) / BLOCK_T, N_FRAMES_C / F_TILE);
    writhe_kernel<<<grid, BLOCK_T>>>(xyz, out);
}